// round 6
// baseline (speedup 1.0000x reference)
#include <cuda_runtime.h>
#include <cuda_bf16.h>
#include <math.h>

// ---------------- problem constants ----------------
#define TT   8
#define NC   512
#define NT   512
#define DD   256
#define HH   8
#define LBL  3
#define NBF  1419
#define EPS_ 1e-4f
#define DN   0.25f          // 256^-0.25
#define DN2  0.0625f        // DN*DN
#define RATIO 0.026549364f  // 1419^-0.5

// ---------------- scratch (device globals; no allocations allowed) ----------------
__device__ float g_xc  [TT*NC*(DD+LBL)];        // concat [4096,259]
__device__ float g_h1  [TT*NC*DD];
__device__ float g_h2  [TT*NC*DD];
__device__ float g_cf  [TT*NC*DD];
__device__ float g_k   [TT*HH*NC*DD];
__device__ float g_v   [TT*HH*NC*DD];
__device__ float g_q   [TT*HH*NT*DD];
__device__ float g_qp  [(long long)TT*HH*NT*NBF];
__device__ float g_kp  [(long long)TT*HH*NC*NBF];
__device__ float g_ksum[TT*HH*NBF];
__device__ float g_kmxp[TT*HH*8];
__device__ float g_dinv[TT*HH*NT];
__device__ float g_ctx [(long long)TT*HH*NBF*DD];
__device__ float g_om  [TT*NT*HH*DD];           // merged [4096,2048]
__device__ float g_rep [TT*NT*DD];

// ---------------- generic tiled fp32 GEMM ----------------
// C[m,n] = alpha * sum_k A(m,k) * B(k,n) (+bias[n]) (relu) (*rowScale[m])
// TA: A stored [K,M] (A[k*lda+m]); else A[m*lda+k]
// TB: B stored [N,K] (B[n*ldb+k]); else B[k*ldb+n]
#define TM_ 64
#define TN_ 64
#define TK_ 16

template<bool TA, bool TB>
__global__ __launch_bounds__(256)
void gemm_kernel(const float* __restrict__ A, const float* __restrict__ B,
                 float* __restrict__ C,
                 int M, int N, int K, int lda, int ldb, int ldc, int cstride,
                 long long sA, long long sB, long long sC,
                 const float* __restrict__ bias, long long sBias,
                 const float* __restrict__ rowScale, long long sRS,
                 float alpha, int relu)
{
    __shared__ float As[TK_][TM_ + 1];
    __shared__ float Bs[TK_][TN_ + 1];

    int z = blockIdx.z;
    A += z * sA; B += z * sB; C += z * sC;
    const float* bptr = bias     ? bias     + z * sBias : nullptr;
    const float* rptr = rowScale ? rowScale + z * sRS   : nullptr;

    int tid = threadIdx.x;
    int tr = tid >> 4;       // 0..15
    int tc = tid & 15;       // 0..15
    int row0 = blockIdx.y * TM_;
    int col0 = blockIdx.x * TN_;

    float acc[4][4];
#pragma unroll
    for (int i = 0; i < 4; i++)
#pragma unroll
        for (int j = 0; j < 4; j++) acc[i][j] = 0.f;

    for (int k0 = 0; k0 < K; k0 += TK_) {
        // ---- load A tile: As[k][m] ----
#pragma unroll
        for (int it = 0; it < 4; ++it) {
            int idx = tid + it * 256;
            if (TA) {
                int kk = idx >> 6, m = idx & 63;
                int gm = row0 + m, gk = k0 + kk;
                As[kk][m] = (gm < M && gk < K) ? A[(long long)gk * lda + gm] : 0.f;
            } else {
                int m = idx >> 4, kk = idx & 15;
                int gm = row0 + m, gk = k0 + kk;
                As[kk][m] = (gm < M && gk < K) ? A[(long long)gm * lda + gk] : 0.f;
            }
        }
        // ---- load B tile: Bs[k][n] ----
#pragma unroll
        for (int it = 0; it < 4; ++it) {
            int idx = tid + it * 256;
            if (TB) {
                int n = idx >> 4, kk = idx & 15;
                int gn = col0 + n, gk = k0 + kk;
                Bs[kk][n] = (gn < N && gk < K) ? B[(long long)gn * ldb + gk] : 0.f;
            } else {
                int kk = idx >> 6, n = idx & 63;
                int gn = col0 + n, gk = k0 + kk;
                Bs[kk][n] = (gn < N && gk < K) ? B[(long long)gk * ldb + gn] : 0.f;
            }
        }
        __syncthreads();
#pragma unroll
        for (int kk = 0; kk < TK_; ++kk) {
            float a[4], b[4];
#pragma unroll
            for (int i = 0; i < 4; i++) a[i] = As[kk][tr * 4 + i];
#pragma unroll
            for (int j = 0; j < 4; j++) b[j] = Bs[kk][tc * 4 + j];
#pragma unroll
            for (int i = 0; i < 4; i++)
#pragma unroll
                for (int j = 0; j < 4; j++) acc[i][j] = fmaf(a[i], b[j], acc[i][j]);
        }
        __syncthreads();
    }

#pragma unroll
    for (int i = 0; i < 4; i++) {
        int r = row0 + tr * 4 + i;
        if (r >= M) continue;
        float rs = rptr ? rptr[r] : 1.f;
#pragma unroll
        for (int j = 0; j < 4; j++) {
            int c = col0 + tc * 4 + j;
            if (c >= N) continue;
            float v = acc[i][j] * alpha;
            if (bptr) v += bptr[c];
            if (relu) v = fmaxf(v, 0.f);
            v *= rs;
            C[(long long)r * ldc + (long long)c * cstride] = v;
        }
    }
}

// ---------------- reductions ----------------
__device__ __forceinline__ float block_reduce_sum(float v) {
    __shared__ float sh[32];
    int lane = threadIdx.x & 31, w = threadIdx.x >> 5;
#pragma unroll
    for (int o = 16; o; o >>= 1) v += __shfl_xor_sync(0xffffffffu, v, o);
    __syncthreads();
    if (lane == 0) sh[w] = v;
    __syncthreads();
    float r = (threadIdx.x < (blockDim.x >> 5)) ? sh[threadIdx.x] : 0.f;
    if (w == 0) {
#pragma unroll
        for (int o = 16; o; o >>= 1) r += __shfl_xor_sync(0xffffffffu, r, o);
        if (lane == 0) sh[0] = r;
    }
    __syncthreads();
    return sh[0];
}

__device__ __forceinline__ float block_reduce_max(float v) {
    __shared__ float sh[32];
    int lane = threadIdx.x & 31, w = threadIdx.x >> 5;
#pragma unroll
    for (int o = 16; o; o >>= 1) v = fmaxf(v, __shfl_xor_sync(0xffffffffu, v, o));
    __syncthreads();
    if (lane == 0) sh[w] = v;
    __syncthreads();
    float r = (threadIdx.x < (blockDim.x >> 5)) ? sh[threadIdx.x] : -INFINITY;
    if (w == 0) {
#pragma unroll
        for (int o = 16; o; o >>= 1) r = fmaxf(r, __shfl_xor_sync(0xffffffffu, r, o));
        if (lane == 0) sh[0] = r;
    }
    __syncthreads();
    return sh[0];
}

// ---------------- elementwise / feature kernels ----------------
__global__ void concat_kernel(const float* __restrict__ x, const float* __restrict__ lbl,
                              float* __restrict__ out) {
    int r = blockIdx.x, tid = threadIdx.x;  // 256 threads
    out[(long long)r * 259 + tid] = x[(long long)r * 256 + tid];
    if (tid < LBL) out[(long long)r * 259 + 256 + tid] = lbl[(long long)r * LBL + tid];
}

// queries: per-row max over F, diag from q row; in-place on dd
__global__ void qfeat_kernel(float* __restrict__ dd, const float* __restrict__ q) {
    long long row = blockIdx.x;
    const float* qr = q + row * DD;
    float* d = dd + row * NBF;
    int tid = threadIdx.x;  // 256
    float qv = qr[tid];
    float diag = 0.5f * block_reduce_sum(qv * qv) * DN2;
    float mx = -INFINITY;
    for (int f = tid; f < NBF; f += 256) mx = fmaxf(mx, d[f]);
    mx = block_reduce_max(mx);
    float sub = diag + mx;
    for (int f = tid; f < NBF; f += 256) d[f] = RATIO * (expf(d[f] - sub) + EPS_);
}

// keys stage 1: partial max per (t,h) over (n,f); 8 n-chunks of 64 rows
__global__ void kmax_kernel(const float* __restrict__ dd, float* __restrict__ kmaxp) {
    int th = blockIdx.y, chunk = blockIdx.x;
    const float* base = dd + ((long long)th * NC + (long long)chunk * 64) * NBF;
    float mx = -INFINITY;
    for (long long i = threadIdx.x; i < (long long)64 * NBF; i += blockDim.x)
        mx = fmaxf(mx, base[i]);
    mx = block_reduce_max(mx);
    if (threadIdx.x == 0) kmaxp[th * 8 + chunk] = mx;
}

// keys stage 2: apply exp with global-(t,h) max; in-place on dd
__global__ void kfeat_kernel(float* __restrict__ dd, const float* __restrict__ k,
                             const float* __restrict__ kmaxp) {
    long long row = blockIdx.x;
    int th = (int)(row >> 9);
    const float* kr = k + row * DD;
    float* d = dd + row * NBF;
    int tid = threadIdx.x;
    float kv = kr[tid];
    float diag = 0.5f * block_reduce_sum(kv * kv) * DN2;
    float mx = -INFINITY;
#pragma unroll
    for (int c = 0; c < 8; c++) mx = fmaxf(mx, kmaxp[th * 8 + c]);
    float sub = diag + mx;
    for (int f = tid; f < NBF; f += 256) d[f] = RATIO * (expf(d[f] - sub) + EPS_);
}

// ksum[th][f] = sum_n kp[th][n][f]
__global__ void ksum_kernel(const float* __restrict__ kp, float* __restrict__ ksum) {
    int th = blockIdx.x;
    const float* base = kp + (long long)th * NC * NBF;
    for (int f = threadIdx.x; f < NBF; f += blockDim.x) {
        float s = 0.f;
        for (int n = 0; n < NC; n++) s += base[(long long)n * NBF + f];
        ksum[(long long)th * NBF + f] = s;
    }
}

// d_inv[row] = 1 / dot(qp[row], ksum[th])
__global__ void dinv_kernel(const float* __restrict__ qp, const float* __restrict__ ksum,
                            float* __restrict__ dinv) {
    long long row = blockIdx.x;
    int th = (int)(row >> 9);
    const float* qr = qp + row * NBF;
    const float* ks = ksum + (long long)th * NBF;
    float s = 0.f;
    for (int f = threadIdx.x; f < NBF; f += 256) s += qr[f] * ks[f];
    s = block_reduce_sum(s);
    if (threadIdx.x == 0) dinv[row] = 1.0f / s;
}

// ---------------- host side ----------------
static float* symaddr(const void* sym) {
    void* p = nullptr;
    cudaGetSymbolAddress(&p, sym);
    return (float*)p;
}

static void gemm(bool ta, bool tb,
                 const float* A, const float* B, float* C,
                 int M, int N, int K, int lda, int ldb, int ldc, int cstride,
                 long long sA, long long sB, long long sC,
                 const float* bias, long long sBias,
                 const float* rs, long long sRS,
                 float alpha, int relu, int batch)
{
    dim3 grid((N + TN_ - 1) / TN_, (M + TM_ - 1) / TM_, batch), blk(256);
    if (!ta && !tb)
        gemm_kernel<false, false><<<grid, blk>>>(A, B, C, M, N, K, lda, ldb, ldc, cstride,
                                                 sA, sB, sC, bias, sBias, rs, sRS, alpha, relu);
    else if (!ta && tb)
        gemm_kernel<false, true><<<grid, blk>>>(A, B, C, M, N, K, lda, ldb, ldc, cstride,
                                                sA, sB, sC, bias, sBias, rs, sRS, alpha, relu);
    else if (ta && !tb)
        gemm_kernel<true, false><<<grid, blk>>>(A, B, C, M, N, K, lda, ldb, ldc, cstride,
                                                sA, sB, sC, bias, sBias, rs, sRS, alpha, relu);
    else
        gemm_kernel<true, true><<<grid, blk>>>(A, B, C, M, N, K, lda, ldb, ldc, cstride,
                                               sA, sB, sC, bias, sBias, rs, sRS, alpha, relu);
}

extern "C" void kernel_launch(void* const* d_in, const int* in_sizes, int n_in,
                              void* d_out, int out_size) {
    (void)in_sizes; (void)n_in; (void)out_size;
    const float* x_ctx = (const float*)d_in[0];
    const float* label = (const float*)d_in[1];
    const float* x_tgt = (const float*)d_in[2];
    const float* W1 = (const float*)d_in[3];  const float* b1 = (const float*)d_in[4];
    const float* W2 = (const float*)d_in[5];  const float* b2 = (const float*)d_in[6];
    const float* W3 = (const float*)d_in[7];  const float* b3 = (const float*)d_in[8];
    const float* Wk = (const float*)d_in[9];  const float* bk = (const float*)d_in[10];
    const float* Wv = (const float*)d_in[11]; const float* bv = (const float*)d_in[12];
    const float* Wq = (const float*)d_in[13]; const float* bq = (const float*)d_in[14];
    const float* Wo = (const float*)d_in[15]; const float* bo = (const float*)d_in[16];
    const float* Wmu = (const float*)d_in[17]; const float* bmu = (const float*)d_in[18];
    const float* proj = (const float*)d_in[19];
    float* out = (float*)d_out;

    float* xc   = symaddr(g_xc);
    float* h1   = symaddr(g_h1);
    float* h2   = symaddr(g_h2);
    float* cf   = symaddr(g_cf);
    float* kbuf = symaddr(g_k);
    float* vbuf = symaddr(g_v);
    float* qbuf = symaddr(g_q);
    float* qp   = symaddr(g_qp);
    float* kp   = symaddr(g_kp);
    float* ksum = symaddr(g_ksum);
    float* kmxp = symaddr(g_kmxp);
    float* dinv = symaddr(g_dinv);
    float* ctx  = symaddr(g_ctx);
    float* om   = symaddr(g_om);
    float* rep  = symaddr(g_rep);

    const int M_ALL = TT * NC;  // 4096

    // 1) task encoder MLP
    concat_kernel<<<M_ALL, 256>>>(x_ctx, label, xc);
    gemm(0, 0, xc, W1, h1, M_ALL, DD, DD + LBL, DD + LBL, DD, DD, 1, 0, 0, 0,
         b1, 0, nullptr, 0, 1.f, 1, 1);
    gemm(0, 0, h1, W2, h2, M_ALL, DD, DD, DD, DD, DD, 1, 0, 0, 0,
         b2, 0, nullptr, 0, 1.f, 1, 1);
    gemm(0, 0, h2, W3, cf, M_ALL, DD, DD, DD, DD, DD, 1, 0, 0, 0,
         b3, 0, nullptr, 0, 1.f, 1, 1);

    // 2) per-head k/v/q projections (layout [t,h,n,e]); batch over t, loop over h
    for (int h = 0; h < HH; h++) {
        long long wo = (long long)h * DD * DD;
        gemm(0, 0, x_ctx, Wk + wo, kbuf + (long long)h * NC * DD,
             NC, DD, DD, DD, DD, DD, 1,
             (long long)NC * DD, 0, (long long)HH * NC * DD,
             bk + h * DD, 0, nullptr, 0, 1.f, 0, TT);
        gemm(0, 0, cf, Wv + wo, vbuf + (long long)h * NC * DD,
             NC, DD, DD, DD, DD, DD, 1,
             (long long)NC * DD, 0, (long long)HH * NC * DD,
             bv + h * DD, 0, nullptr, 0, 1.f, 0, TT);
        gemm(0, 0, x_tgt, Wq + wo, qbuf + (long long)h * NT * DD,
             NT, DD, DD, DD, DD, DD, 1,
             (long long)NT * DD, 0, (long long)HH * NT * DD,
             bq + h * DD, 0, nullptr, 0, 1.f, 0, TT);
    }

    // 3) FAVOR+ feature projections: dd = (x * dn) @ proj^T, batch over (t,h)
    gemm(0, 1, qbuf, proj, qp, NT, NBF, DD, DD, DD, NBF, 1,
         (long long)NT * DD, 0, (long long)NT * NBF,
         nullptr, 0, nullptr, 0, DN, 0, TT * HH);
    gemm(0, 1, kbuf, proj, kp, NC, NBF, DD, DD, DD, NBF, 1,
         (long long)NC * DD, 0, (long long)NC * NBF,
         nullptr, 0, nullptr, 0, DN, 0, TT * HH);

    // 4) softmax-kernel transforms
    kmax_kernel<<<dim3(8, TT * HH), 256>>>(kp, kmxp);
    qfeat_kernel<<<TT * HH * NT, 256>>>(qp, qbuf);
    kfeat_kernel<<<TT * HH * NC, 256>>>(kp, kbuf, kmxp);
    ksum_kernel<<<TT * HH, 512>>>(kp, ksum);
    dinv_kernel<<<TT * HH * NT, 256>>>(qp, ksum, dinv);

    // 5) ctx[t,h] = kp^T @ v : [1419,256] = [512,1419]^T @ [512,256], batch 64
    gemm(1, 0, kp, vbuf, ctx, NBF, DD, NC, NBF, DD, DD, 1,
         (long long)NC * NBF, (long long)NC * DD, (long long)NBF * DD,
         nullptr, 0, nullptr, 0, 1.f, 0, TT * HH);

    // 6) out = (qp @ ctx) * d_inv, stored head-interleaved into om[t,n,e*H+h]
    for (int h = 0; h < HH; h++) {
        gemm(0, 0, qp + (long long)h * NT * NBF, ctx + (long long)h * NBF * DD, om + h,
             NT, DD, NBF, NBF, DD, HH * DD, HH,
             (long long)HH * NT * NBF, (long long)HH * NBF * DD, (long long)NT * HH * DD,
             nullptr, 0, dinv + (long long)h * NT, (long long)HH * NT, 1.f, 0, TT);
    }

    // 7) rep = om @ Wo + bo ; mu = rep @ Wmu + bmu
    gemm(0, 0, om, Wo, rep, M_ALL, DD, HH * DD, HH * DD, DD, DD, 1,
         0, 0, 0, bo, 0, nullptr, 0, 1.f, 0, 1);
    gemm(0, 0, rep, Wmu, out, M_ALL, DD, DD, DD, DD, DD, 1,
         0, 0, 0, bmu, 0, nullptr, 0, 1.f, 0, 1);
}

// round 9
// speedup vs baseline: 2.9909x; 2.9909x over previous
#include <cuda_runtime.h>
#include <cuda_bf16.h>
#include <math.h>
#include <stdint.h>

#define TT 8
#define NCC 512
#define NTT 512
#define DD 256
#define HH 8
#define LBL 3
#define NBF 1419
#define EPS_ 1e-4f
#define DN 0.25f
#define DN2 0.0625f
#define RATIO 0.026549364f

typedef __nv_bfloat16 bf;

// ---------------- fp32 scratch ----------------
__device__ float g_xc[TT*NCC*(DD+LBL)];
__device__ float g_h1[TT*NCC*DD];
__device__ float g_h2[TT*NCC*DD];
__device__ float g_cf[TT*NCC*DD];
__device__ float g_k[TT*HH*NCC*DD];
__device__ float g_v[TT*HH*NCC*DD];
__device__ float g_q[TT*HH*NTT*DD];
__device__ float g_qp[(long long)TT*HH*NTT*NBF];
__device__ float g_kp[(long long)TT*HH*NCC*NBF];
__device__ float g_ksum[TT*HH*NBF];
__device__ float g_kmxp[TT*HH*8];
__device__ float g_dinv[TT*HH*NTT];
__device__ float g_ctx[(long long)TT*HH*NBF*DD];
__device__ float g_om[TT*NTT*HH*DD];
__device__ float g_rep[TT*NTT*DD];

// ---------------- bf16 operand pools (reused across phases) ----------------
#define PA_SZ 50331648LL   // max A tiles: kp^T = 64*12*8*8192
#define PB_SZ 24117248LL   // max B tiles: ctx^T = 64*2*23*8192
__device__ __align__(16) bf pAh[PA_SZ], pAl[PA_SZ];
__device__ __align__(16) bf pBh[PB_SZ], pBl[PB_SZ];

// ---------------- PTX helpers ----------------
__device__ __forceinline__ uint32_t smem_u32(const void* p) {
    uint32_t a;
    asm("{ .reg .u64 t; cvta.to.shared.u64 t, %1; cvt.u32.u64 %0, t; }" : "=r"(a) : "l"(p));
    return a;
}
__device__ __forceinline__ void cpa16(uint32_t s, const void* g) {
    asm volatile("cp.async.cg.shared.global [%0], [%1], 16;" :: "r"(s), "l"(g));
}
__device__ __forceinline__ void ldsm4(uint32_t* r, uint32_t addr) {
    asm volatile("ldmatrix.sync.aligned.m8n8.x4.shared.b16 {%0,%1,%2,%3}, [%4];"
        : "=r"(r[0]), "=r"(r[1]), "=r"(r[2]), "=r"(r[3]) : "r"(addr));
}
__device__ __forceinline__ void mma16816(float* c, const uint32_t* a,
                                         uint32_t b0, uint32_t b1) {
    asm volatile("mma.sync.aligned.m16n8k16.row.col.f32.bf16.bf16.f32 "
        "{%0,%1,%2,%3}, {%4,%5,%6,%7}, {%8,%9}, {%0,%1,%2,%3};"
        : "+f"(c[0]), "+f"(c[1]), "+f"(c[2]), "+f"(c[3])
        : "r"(a[0]), "r"(a[1]), "r"(a[2]), "r"(a[3]), "r"(b0), "r"(b1));
}
__device__ __forceinline__ uint32_t swz(uint32_t off) {
    return off ^ ((off >> 3) & 0x70);
}

// ======= fp32 -> (hi,lo) bf16, tiled 128x64, SW128-swizzled =======
// src element (r,c) of logical operand at src[(z>>3)*szh + (z&7)*szl + r*rs + c*cs]
__global__ __launch_bounds__(256) void conv_kernel(
    const float* __restrict__ src, long long szh, long long szl,
    int rs_, int cs_, int R, int C, int RT, int CT,
    bf* __restrict__ hi, bf* __restrict__ lo)
{
    __shared__ float sh[128][65];
    int tile = blockIdx.x;
    int ct = tile % CT, rt = (tile / CT) % RT, z = tile / (CT * RT);
    const float* s = src + (long long)(z >> 3) * szh + (long long)(z & 7) * szl;
    int r0 = rt * 128, c0 = ct * 64, tid = threadIdx.x;
    if (rs_ == 1) {
#pragma unroll 4
        for (int it = 0; it < 32; ++it) {
            int e = it * 256 + tid, r = e & 127, c = e >> 7;
            int gr = r0 + r, gc = c0 + c;
            sh[r][c] = (gr < R && gc < C) ? s[(long long)gr + (long long)gc * cs_] : 0.f;
        }
    } else {
#pragma unroll 4
        for (int it = 0; it < 32; ++it) {
            int e = it * 256 + tid, r = e >> 6, c = e & 63;
            int gr = r0 + r, gc = c0 + c;
            sh[r][c] = (gr < R && gc < C) ? s[(long long)gr * rs_ + (long long)gc * cs_] : 0.f;
        }
    }
    __syncthreads();
    long long tb = (long long)tile * 8192;
#pragma unroll
    for (int it = 0; it < 4; ++it) {
        int p0 = (it * 256 + tid) * 8;
        uint32_t lb = swz((uint32_t)(p0 * 2));   // self-inverse
        int q0 = lb >> 1, r = q0 >> 6, c = q0 & 63;
        bf hv[8], lv[8];
#pragma unroll
        for (int j = 0; j < 8; ++j) {
            float x = sh[r][c + j];
            bf h = __float2bfloat16(x);
            hv[j] = h;
            lv[j] = __float2bfloat16(x - __bfloat162float(h));
        }
        *(uint4*)(hi + tb + p0) = *(const uint4*)hv;
        *(uint4*)(lo + tb + p0) = *(const uint4*)lv;
    }
}

// ======= split-bf16 GEMM via mma.sync: D = alpha*A@B^T (+bias)(relu)(*rowScale) =======
// Operand tiles: 128 rows x 64 k (bf16, SW128-swizzled, 16KB each).
// Stage = [Ah 16K][Al 16K][Bh 16K][Bl 16K] = 64KB, double buffered.
#define SMEM_DYN (2 * 65536)

__global__ __launch_bounds__(256, 1)
void tgemm(const bf* __restrict__ Ahi, const bf* __restrict__ Alo,
           const bf* __restrict__ Bhi, const bf* __restrict__ Blo,
           float* __restrict__ C, int Mv, int Nv, int KT,
           long long sAh, long long sAl, long long sBh, long long sBl,
           long long sCh, long long sCl, int ldc, int cstride,
           const float* __restrict__ bias, long long sbh, long long sbl,
           const float* __restrict__ rsc, long long srh, long long srl,
           float alpha, int relu)
{
    extern __shared__ __align__(16) char dsm[];
    uint32_t base = smem_u32(dsm);

    int tid = threadIdx.x, wid = tid >> 5, lane = tid & 31;
    int z = blockIdx.z, mt = blockIdx.y, nt = blockIdx.x;
    int zh = z >> 3, zl = z & 7;

    const char* Ah = (const char*)(Ahi + zh * sAh + zl * sAl + (long long)mt * KT * 8192);
    const char* Al = (const char*)(Alo + zh * sAh + zl * sAl + (long long)mt * KT * 8192);
    const char* Bh = (const char*)(Bhi + zh * sBh + zl * sBl + (long long)nt * KT * 8192);
    const char* Bl = (const char*)(Blo + zh * sBh + zl * sBl + (long long)nt * KT * 8192);

    // warp layout: 2 (m) x 4 (n); warp tile 64x32
    int warp_m = wid >> 2, warp_n = wid & 3;
    // ldmatrix lane offsets (logical bytes within 128x64 tile, 128B rows)
    uint32_t aOff = (uint32_t)(warp_m * 64 + (lane & 15)) * 128 + ((lane >> 4) << 4);
    uint32_t bOff = (uint32_t)(warp_n * 32 + (lane & 7) + ((lane >> 4) << 3)) * 128
                  + (((lane >> 3) & 1) << 4);

    float acc[4][4][4];
#pragma unroll
    for (int i = 0; i < 4; i++)
#pragma unroll
        for (int j = 0; j < 4; j++)
#pragma unroll
            for (int l = 0; l < 4; l++) acc[i][j][l] = 0.f;

    // prologue: stage 0 <- chunk 0
    {
        uint32_t so = base;
#pragma unroll
        for (int i = 0; i < 4; ++i) {
            uint32_t off = tid * 16 + i * 4096;
            cpa16(so + off,         Ah + off);
            cpa16(so + 16384 + off, Al + off);
            cpa16(so + 32768 + off, Bh + off);
            cpa16(so + 49152 + off, Bl + off);
        }
        asm volatile("cp.async.commit_group;" ::: "memory");
    }

    for (int kt = 0; kt < KT; ++kt) {
        int s = kt & 1;
        if (kt + 1 < KT) {
            uint32_t so = base + (s ^ 1) * 65536;
            long long kb = (long long)(kt + 1) * 16384;
#pragma unroll
            for (int i = 0; i < 4; ++i) {
                uint32_t off = tid * 16 + i * 4096;
                cpa16(so + off,         Ah + kb + off);
                cpa16(so + 16384 + off, Al + kb + off);
                cpa16(so + 32768 + off, Bh + kb + off);
                cpa16(so + 49152 + off, Bl + kb + off);
            }
            asm volatile("cp.async.commit_group;" ::: "memory");
            asm volatile("cp.async.wait_group 1;" ::: "memory");
        } else {
            asm volatile("cp.async.wait_group 0;" ::: "memory");
        }
        __syncthreads();

        uint32_t sb = base + s * 65536;
#pragma unroll
        for (int ks = 0; ks < 4; ++ks) {
            uint32_t kb = ks * 32;
            uint32_t a_h[4][4], a_l[4][4], b_h[2][4], b_l[2][4];
#pragma unroll
            for (int m = 0; m < 4; ++m) {
                uint32_t o = swz(aOff + m * 2048 + kb);
                ldsm4(a_h[m], sb + o);
                ldsm4(a_l[m], sb + 16384 + o);
            }
#pragma unroll
            for (int p = 0; p < 2; ++p) {
                uint32_t o = swz(bOff + p * 2048 + kb);
                ldsm4(b_h[p], sb + 32768 + o);
                ldsm4(b_l[p], sb + 49152 + o);
            }
#pragma unroll
            for (int m = 0; m < 4; ++m)
#pragma unroll
                for (int p = 0; p < 2; ++p)
#pragma unroll
                    for (int sub = 0; sub < 2; ++sub) {
                        int n = p * 2 + sub;
                        mma16816(acc[m][n], a_h[m], b_h[p][sub*2], b_h[p][sub*2+1]);
                        mma16816(acc[m][n], a_h[m], b_l[p][sub*2], b_l[p][sub*2+1]);
                        mma16816(acc[m][n], a_l[m], b_h[p][sub*2], b_h[p][sub*2+1]);
                    }
        }
        __syncthreads();
    }

    // ---- epilogue ----
    float* Cp = C + (long long)zh * sCh + (long long)zl * sCl;
    const float* bp = bias ? bias + zh * sbh + zl * sbl : nullptr;
    const float* rp = rsc  ? rsc  + zh * srh + zl * srl : nullptr;
    int g = lane >> 2, t4 = lane & 3;
#pragma unroll
    for (int m = 0; m < 4; ++m) {
        int r0 = mt * 128 + warp_m * 64 + m * 16 + g;   // rows r0, r0+8
        float rv0 = (rp && r0     < Mv) ? rp[r0]     : 1.f;
        float rv1 = (rp && r0 + 8 < Mv) ? rp[r0 + 8] : 1.f;
#pragma unroll
        for (int n = 0; n < 4; ++n) {
            int c0 = nt * 128 + warp_n * 32 + n * 8 + t4 * 2;
#pragma unroll
            for (int e = 0; e < 2; ++e) {
                int col = c0 + e;
                if (col >= Nv) continue;
                float badd = bp ? bp[col] : 0.f;
                if (r0 < Mv) {
                    float v = acc[m][n][e] * alpha + badd;
                    if (relu) v = fmaxf(v, 0.f);
                    Cp[(long long)r0 * ldc + (long long)col * cstride] = v * rv0;
                }
                if (r0 + 8 < Mv) {
                    float v = acc[m][n][2 + e] * alpha + badd;
                    if (relu) v = fmaxf(v, 0.f);
                    Cp[(long long)(r0 + 8) * ldc + (long long)col * cstride] = v * rv1;
                }
            }
        }
    }
}

// ---------------- reductions ----------------
__device__ __forceinline__ float blk_sum(float v) {
    __shared__ float sh[32];
    int lane = threadIdx.x & 31, w = threadIdx.x >> 5;
#pragma unroll
    for (int o = 16; o; o >>= 1) v += __shfl_xor_sync(0xffffffffu, v, o);
    __syncthreads();
    if (lane == 0) sh[w] = v;
    __syncthreads();
    float r = (threadIdx.x < (blockDim.x >> 5)) ? sh[threadIdx.x] : 0.f;
    if (w == 0) {
#pragma unroll
        for (int o = 16; o; o >>= 1) r += __shfl_xor_sync(0xffffffffu, r, o);
        if (lane == 0) sh[0] = r;
    }
    __syncthreads();
    return sh[0];
}
__device__ __forceinline__ float blk_max(float v) {
    __shared__ float sh[32];
    int lane = threadIdx.x & 31, w = threadIdx.x >> 5;
#pragma unroll
    for (int o = 16; o; o >>= 1) v = fmaxf(v, __shfl_xor_sync(0xffffffffu, v, o));
    __syncthreads();
    if (lane == 0) sh[w] = v;
    __syncthreads();
    float r = (threadIdx.x < (blockDim.x >> 5)) ? sh[threadIdx.x] : -INFINITY;
    if (w == 0) {
#pragma unroll
        for (int o = 16; o; o >>= 1) r = fmaxf(r, __shfl_xor_sync(0xffffffffu, r, o));
        if (lane == 0) sh[0] = r;
    }
    __syncthreads();
    return sh[0];
}

// ---------------- elementwise ----------------
__global__ void concat_kernel(const float* __restrict__ x, const float* __restrict__ l,
                              float* __restrict__ o) {
    int r = blockIdx.x, t = threadIdx.x;
    o[(long long)r * 259 + t] = x[(long long)r * 256 + t];
    if (t < LBL) o[(long long)r * 259 + 256 + t] = l[(long long)r * LBL + t];
}
__global__ void qfeat_kernel(float* __restrict__ dd, const float* __restrict__ q) {
    long long row = blockIdx.x;
    const float* qr = q + row * DD;
    float* d = dd + row * NBF;
    int t = threadIdx.x;
    float qv = qr[t];
    float diag = 0.5f * blk_sum(qv * qv) * DN2;
    float mx = -INFINITY;
    for (int f = t; f < NBF; f += 256) mx = fmaxf(mx, d[f]);
    mx = blk_max(mx);
    float sub = diag + mx;
    for (int f = t; f < NBF; f += 256) d[f] = RATIO * (__expf(d[f] - sub) + EPS_);
}
__global__ void kmax_kernel(const float* __restrict__ dd, float* __restrict__ km) {
    int th = blockIdx.y, ch = blockIdx.x;
    const float* b = dd + ((long long)th * NCC + (long long)ch * 64) * NBF;
    float mx = -INFINITY;
    for (long long i = threadIdx.x; i < (long long)64 * NBF; i += blockDim.x)
        mx = fmaxf(mx, b[i]);
    mx = blk_max(mx);
    if (threadIdx.x == 0) km[th * 8 + ch] = mx;
}
__global__ void kfeat_kernel(float* __restrict__ dd, const float* __restrict__ k,
                             const float* __restrict__ km) {
    long long row = blockIdx.x;
    int th = (int)(row >> 9), t = threadIdx.x;
    const float* kr = k + row * DD;
    float* d = dd + row * NBF;
    float kv = kr[t];
    float diag = 0.5f * blk_sum(kv * kv) * DN2;
    float mx = -INFINITY;
#pragma unroll
    for (int c = 0; c < 8; c++) mx = fmaxf(mx, km[th * 8 + c]);
    float sub = diag + mx;
    for (int f = t; f < NBF; f += 256) d[f] = RATIO * (__expf(d[f] - sub) + EPS_);
}
__global__ void ksum_kernel(const float* __restrict__ kp, float* __restrict__ ks) {
    int th = blockIdx.y, f = blockIdx.x * 128 + threadIdx.x;
    if (f >= NBF) return;
    const float* b = kp + (long long)th * NCC * NBF + f;
    float s = 0.f;
    for (int n = 0; n < NCC; n++) s += b[(long long)n * NBF];
    ks[(long long)th * NBF + f] = s;
}
__global__ void dinv_kernel(const float* __restrict__ qp, const float* __restrict__ ks,
                            float* __restrict__ di) {
    long long row = blockIdx.x;
    int th = (int)(row >> 9);
    const float* qr = qp + row * NBF;
    const float* k = ks + (long long)th * NBF;
    float s = 0.f;
    for (int f = threadIdx.x; f < NBF; f += 256) s += qr[f] * k[f];
    s = blk_sum(s);
    if (threadIdx.x == 0) di[row] = 1.0f / s;
}

// ---------------- host ----------------
static float* symf(const void* s) { void* p = nullptr; cudaGetSymbolAddress(&p, s); return (float*)p; }
static bf*    symb(const void* s) { void* p = nullptr; cudaGetSymbolAddress(&p, s); return (bf*)p; }

static void conv(const float* src, long long szh, long long szl, int rs, int cs,
                 int R, int C, int RT, int CT, bf* hi, bf* lo, int nb) {
    conv_kernel<<<nb * RT * CT, 256>>>(src, szh, szl, rs, cs, R, C, RT, CT, hi, lo);
}
static void tg(const bf* Ah, const bf* Al, const bf* Bh, const bf* Bl, float* C,
               int Mv, int Nv, int KT, int MT, int NT, int batch,
               long long sAh, long long sAl, long long sBh, long long sBl,
               long long sCh, long long sCl, int ldc, int cstr,
               const float* bias, long long sbh, long long sbl,
               const float* rs, long long srh, long long srl, float alpha, int relu) {
    dim3 grid(NT, MT, batch);
    tgemm<<<grid, 256, SMEM_DYN>>>(Ah, Al, Bh, Bl, C, Mv, Nv, KT, sAh, sAl, sBh, sBl,
                                   sCh, sCl, ldc, cstr, bias, sbh, sbl, rs, srh, srl, alpha, relu);
}

extern "C" void kernel_launch(void* const* d_in, const int* in_sizes, int n_in,
                              void* d_out, int out_size) {
    (void)in_sizes; (void)n_in; (void)out_size;
    const float* x_ctx = (const float*)d_in[0];
    const float* label = (const float*)d_in[1];
    const float* x_tgt = (const float*)d_in[2];
    const float* W1 = (const float*)d_in[3];  const float* b1 = (const float*)d_in[4];
    const float* W2 = (const float*)d_in[5];  const float* b2 = (const float*)d_in[6];
    const float* W3 = (const float*)d_in[7];  const float* b3 = (const float*)d_in[8];
    const float* Wk = (const float*)d_in[9];  const float* bk = (const float*)d_in[10];
    const float* Wv = (const float*)d_in[11]; const float* bv = (const float*)d_in[12];
    const float* Wq = (const float*)d_in[13]; const float* bq = (const float*)d_in[14];
    const float* Wo = (const float*)d_in[15]; const float* bo = (const float*)d_in[16];
    const float* Wmu = (const float*)d_in[17]; const float* bmu = (const float*)d_in[18];
    const float* proj = (const float*)d_in[19];
    float* out = (float*)d_out;

    cudaFuncSetAttribute(tgemm, cudaFuncAttributeMaxDynamicSharedMemorySize, SMEM_DYN);

    float *xc = symf(g_xc), *h1 = symf(g_h1), *h2 = symf(g_h2), *cf = symf(g_cf);
    float *kb = symf(g_k), *vb = symf(g_v), *qb = symf(g_q);
    float *qp = symf(g_qp), *kp = symf(g_kp), *ksum = symf(g_ksum);
    float *kmxp = symf(g_kmxp), *dinv = symf(g_dinv), *ctx = symf(g_ctx);
    float *om = symf(g_om), *rep = symf(g_rep);
    bf *Ah = symb(pAh), *Al = symb(pAl), *Bh = symb(pBh), *Bl = symb(pBl);

    // 1) task encoder MLP
    concat_kernel<<<TT * NCC, 256>>>(x_ctx, label, xc);
    conv(xc, 0, 0, 259, 1, 4096, 259, 32, 5, Ah, Al, 1);
    conv(W1, 0, 0, 1, 256, 256, 259, 2, 5, Bh, Bl, 1);           // B[n,k]=W1[k*256+n]
    tg(Ah, Al, Bh, Bl, h1, 4096, 256, 5, 32, 2, 1, 0,0,0,0, 0,0, 256,1, b1,0,0, nullptr,0,0, 1.f, 1);
    conv(h1, 0, 0, 256, 1, 4096, 256, 32, 4, Ah, Al, 1);
    conv(W2, 0, 0, 1, 256, 256, 256, 2, 4, Bh, Bl, 1);
    tg(Ah, Al, Bh, Bl, h2, 4096, 256, 4, 32, 2, 1, 0,0,0,0, 0,0, 256,1, b2,0,0, nullptr,0,0, 1.f, 1);
    conv(h2, 0, 0, 256, 1, 4096, 256, 32, 4, Ah, Al, 1);
    conv(W3, 0, 0, 1, 256, 256, 256, 2, 4, Bh, Bl, 1);
    tg(Ah, Al, Bh, Bl, cf, 4096, 256, 4, 32, 2, 1, 0,0,0,0, 0,0, 256,1, b3,0,0, nullptr,0,0, 1.f, 1);

    // 2) per-head k/v/q projections -> [t,h,n,e]; z = t*8+h (A by t, B by h)
    conv(x_ctx, 0, 0, 256, 1, 4096, 256, 32, 4, Ah, Al, 1);
    conv(Wk, 0, 65536, 1, 256, 256, 256, 2, 4, Bh, Bl, 8);       // B[n=e,k=d]=Wk[h][d*256+e]
    tg(Ah, Al, Bh, Bl, kb, 512, 256, 4, 4, 2, 64, 131072,0, 0,65536,
       1048576,131072, 256,1, bk,0,256, nullptr,0,0, 1.f, 0);
    conv(cf, 0, 0, 256, 1, 4096, 256, 32, 4, Ah, Al, 1);
    conv(Wv, 0, 65536, 1, 256, 256, 256, 2, 4, Bh, Bl, 8);
    tg(Ah, Al, Bh, Bl, vb, 512, 256, 4, 4, 2, 64, 131072,0, 0,65536,
       1048576,131072, 256,1, bv,0,256, nullptr,0,0, 1.f, 0);
    conv(x_tgt, 0, 0, 256, 1, 4096, 256, 32, 4, Ah, Al, 1);
    conv(Wq, 0, 65536, 1, 256, 256, 256, 2, 4, Bh, Bl, 8);
    tg(Ah, Al, Bh, Bl, qb, 512, 256, 4, 4, 2, 64, 131072,0, 0,65536,
       1048576,131072, 256,1, bq,0,256, nullptr,0,0, 1.f, 0);

    // 3) FAVOR+ projections: dd = DN * X @ proj^T
    conv(proj, 0, 0, 256, 1, 1419, 256, 12, 4, Bh, Bl, 1);       // B[n=f,k=d]=proj[f*256+d]
    conv(qb, 0, 0, 256, 1, 32768, 256, 256, 4, Ah, Al, 1);
    tg(Ah, Al, Bh, Bl, qp, 32768, NBF, 4, 256, 12, 1, 0,0,0,0, 0,0, NBF,1,
       nullptr,0,0, nullptr,0,0, DN, 0);
    conv(kb, 0, 0, 256, 1, 32768, 256, 256, 4, Ah, Al, 1);
    tg(Ah, Al, Bh, Bl, kp, 32768, NBF, 4, 256, 12, 1, 0,0,0,0, 0,0, NBF,1,
       nullptr,0,0, nullptr,0,0, DN, 0);

    // 4) softmax-kernel transforms
    kmax_kernel<<<dim3(8, TT * HH), 256>>>(kp, kmxp);
    kfeat_kernel<<<TT * HH * NCC, 256>>>(kp, kb, kmxp);
    qfeat_kernel<<<TT * HH * NTT, 256>>>(qp, qb);
    ksum_kernel<<<dim3(12, TT * HH), 128>>>(kp, ksum);
    dinv_kernel<<<TT * HH * NTT, 256>>>(qp, ksum, dinv);

    // 5) ctx[z] = kp[z]^T @ v[z]   (M=1419, K=512, N=256, 64 batches)
    conv(kp, 8LL*726528, 726528, 1, 1419, 1419, 512, 12, 8, Ah, Al, 64);  // A[f,n]=kp[z][n][f]
    conv(vb, 8LL*131072, 131072, 1, 256, 256, 512, 2, 8, Bh, Bl, 64);     // B[e,n]=v[z][n][e]
    tg(Ah, Al, Bh, Bl, ctx, NBF, 256, 8, 12, 2, 64, 8LL*786432,786432, 8LL*131072,131072,
       8LL*363264,363264, 256,1, nullptr,0,0, nullptr,0,0, 1.f, 0);

    // 6) om = (qp @ ctx) * dinv, head-interleaved store om[t][n][e*8+h]
    conv(qp, 8LL*726528, 726528, 1419, 1, 512, 1419, 4, 23, Ah, Al, 64);  // A[n,f]
    conv(ctx, 8LL*363264, 363264, 1, 256, 256, 1419, 2, 23, Bh, Bl, 64);  // B[e,f]=ctx[z][f][e]
    tg(Ah, Al, Bh, Bl, om, 512, 256, 23, 4, 2, 64, 8LL*753664,753664, 8LL*376832,376832,
       1048576,1, 2048,8, nullptr,0,0, dinv,4096,512, 1.f, 0);

    // 7) rep = om @ Wo + bo ; out = rep @ Wmu + bmu
    conv(om, 0, 0, 2048, 1, 4096, 2048, 32, 32, Ah, Al, 1);
    conv(Wo, 0, 0, 1, 256, 256, 2048, 2, 32, Bh, Bl, 1);
    tg(Ah, Al, Bh, Bl, rep, 4096, 256, 32, 32, 2, 1, 0,0,0,0, 0,0, 256,1,
       bo,0,0, nullptr,0,0, 1.f, 0);
    conv(rep, 0, 0, 256, 1, 4096, 256, 32, 4, Ah, Al, 1);
    conv(Wmu, 0, 0, 1, 256, 256, 256, 2, 4, Bh, Bl, 1);
    tg(Ah, Al, Bh, Bl, out, 4096, 256, 4, 32, 2, 1, 0,0,0,0, 0,0, 256,1,
       bmu,0,0, nullptr,0,0, 1.f, 0);
}